// round 5
// baseline (speedup 1.0000x reference)
#include <cuda_runtime.h>
#include <cstdint>

#define BATCH   32768
#define NUM_IN  256
#define NUM_HID 512
#define NUM_OUT 64
#define M_NODES 576
#define N_NODES 832
#define KFAN    32
#define COLS    32
#define THREADS 512            // 16 warps
#define SLOTS   16             // nodes per round (1 per warp)
#define RSTRIDE 800            // words/round: 256 src16 + 512 w + 16 bias + 16 tgt
#define RMAX    576

// round-major param blob, per round r at r*RSTRIDE:
//   [0..256)    src16  (slot*16 + j): two u16 (pred*32) offsets per word
//   [256..768)  w      (256 + slot*32 + k)
//   [768..784)  bias per slot
//   [784..800)  target smem offset (tgt_row*32) per slot, -1 = dummy
__device__ float g_blob[(size_t)RMAX * RSTRIDE];
__device__ int   g_sched[RMAX * SLOTS];
__device__ int   g_nrounds;

// ---------------------------------------------------------------------------
// Kernel A: greedy list scheduling. 1 block, 576 threads (one per node).
// Branch-free pred scan (pipelined LDS), warp-aggregated atomics,
// terminate when a round schedules nothing (DAG => all done).
// ---------------------------------------------------------------------------
__global__ __launch_bounds__(M_NODES)
void schedule_kernel(const int* __restrict__ src) {
    __shared__ short rnd[M_NODES];                 // assigned round or -1
    __shared__ unsigned short plist[M_NODES * KFAN];
    __shared__ int picked;

    const int t = threadIdx.x;
    const unsigned lane = t & 31;

    int np = 0;
    for (int k = 0; k < KFAN; k++) {
        int s = src[t * KFAN + k];
        if (s >= NUM_IN) plist[t * KFAN + np++] = (unsigned short)(s - NUM_IN);
    }
    rnd[t] = -1;
    for (int i = t; i < RMAX * SLOTS; i += M_NODES) g_sched[i] = -1;
    __syncthreads();

    int myrnd = -1;
    for (int r = 0; r < RMAX; r++) {
        // scan: any unscheduled pred? (-1 propagates sign via OR; no branches)
        bool ready = false;
        if (myrnd < 0) {
            int bad = 0;
            for (int j = 0; j < np; j++)
                bad |= (int)rnd[plist[t * KFAN + j]];
            ready = (bad >= 0);
        }
        if (t == 0) picked = 0;
        __syncthreads();                           // scans done, picked reset

        unsigned bal = __ballot_sync(0xFFFFFFFFu, ready);
        int base = 0;
        if (lane == 0 && bal) base = atomicAdd(&picked, __popc(bal));
        base = __shfl_sync(0xFFFFFFFFu, base, 0);
        if (ready) {
            int p = base + __popc(bal & ((1u << lane) - 1u));
            if (p < SLOTS) {
                myrnd = r;
                rnd[t] = (short)r;                 // safe: scans finished pre-barrier
                g_sched[r * SLOTS + p] = t;
            }
        }
        __syncthreads();                           // picked final, writes done
        if (picked == 0) {                         // nothing ready => all scheduled
            if (t == 0) g_nrounds = r;
            return;
        }
    }
    if (t == 0) g_nrounds = RMAX;
}

// ---------------------------------------------------------------------------
// Kernel B: grid-parallel blob fill, one block per (used) round.
// ---------------------------------------------------------------------------
__global__ __launch_bounds__(256)
void blob_fill_kernel(const int* __restrict__ src,
                      const float* __restrict__ w,
                      const float* __restrict__ bias) {
    const int r = blockIdx.x;
    if (r >= g_nrounds) return;
    float* Pr = g_blob + (size_t)r * RSTRIDE;
    const int tid = threadIdx.x;

    // src16: premultiplied (pred*32) offsets
    {
        int slot = tid >> 4, j = tid & 15;
        int nd = g_sched[r * SLOTS + slot];
        unsigned v = 0;
        if (nd >= 0) {
            unsigned a = (unsigned)src[nd * KFAN + 2 * j] * COLS;
            unsigned b = (unsigned)src[nd * KFAN + 2 * j + 1] * COLS;
            v = (a & 0xFFFFu) | (b << 16);
        }
        ((unsigned*)Pr)[slot * 16 + j] = v;
    }
    #pragma unroll
    for (int u = 0; u < 2; u++) {
        int q = tid + u * 256;
        int slot = q >> 5, k = q & 31;
        int nd = g_sched[r * SLOTS + slot];
        Pr[256 + slot * 32 + k] = (nd >= 0) ? w[nd * KFAN + k] : 0.0f;
    }
    if (tid < SLOTS) {
        int nd = g_sched[r * SLOTS + tid];
        Pr[768 + tid] = (nd >= 0) ? bias[nd] : 0.0f;
        ((int*)Pr)[784 + tid] = (nd >= 0) ? (NUM_IN + nd) * COLS : -1;
    }
}

// ---------------------------------------------------------------------------
// Main kernel: 1024 blocks x 512 threads, 32 batch columns per block,
// 2 blocks/SM. Full state in SMEM; 16 independent nodes/round (warp/node).
// ---------------------------------------------------------------------------
#define ST_WORDS    (N_NODES * COLS)               // 26624
#define STAGE_WORDS (2 * RSTRIDE)                  // 1600 (also covers 32x33 staging)
#define TOTAL_WORDS (ST_WORDS + STAGE_WORDS)       // 28224 -> 112896 B

extern __shared__ float smem_f[];

__device__ __forceinline__ void cp16(void* sdst, const void* gsrc) {
    uint32_t s = (uint32_t)__cvta_generic_to_shared(sdst);
    asm volatile("cp.async.cg.shared.global [%0], [%1], 16;\n" :: "r"(s), "l"(gsrc));
}

__global__ __launch_bounds__(THREADS, 2)
void neat_main_kernel(const float* __restrict__ x,
                      float* __restrict__ out) {
    float* st    = smem_f;                 // [N_NODES][COLS]
    float* stage = smem_f + ST_WORDS;      // param double buffer / transpose staging

    const int tid  = threadIdx.x;
    const int wid  = tid >> 5;
    const int lane = tid & 31;
    const int b0   = blockIdx.x * COLS;
    const int R    = g_nrounds;

    // ---- input transpose: x[b][n] -> st[n][col], 8 chunks of 32 inputs ----
    for (int ch = 0; ch < 8; ch++) {
        const int nc0 = ch * 32;
        __syncthreads();
        #pragma unroll
        for (int i = 0; i < 2; i++) {
            int idx = tid + i * THREADS;
            int row = idx >> 5, c = idx & 31;
            stage[row * 33 + c] = x[(size_t)(b0 + row) * NUM_IN + nc0 + c];
        }
        __syncthreads();
        #pragma unroll
        for (int i = 0; i < 2; i++) {
            int idx = tid + i * THREADS;
            int n = idx >> 5, col = idx & 31;
            st[(nc0 + n) * COLS + col] = stage[col * 33 + n];
        }
    }
    __syncthreads();

    // ---- prefetch round 0 params ----
    if (tid < RSTRIDE / 4) cp16(stage + tid * 4, g_blob + tid * 4);
    asm volatile("cp.async.commit_group;\n");
    asm volatile("cp.async.wait_group 0;\n" ::: "memory");
    __syncthreads();

    float* stcol = st + lane;

    // ---- main rounds: warp wid evaluates slot wid over 32 columns ----
    for (int r = 0; r < R; r++) {
        float* P  = stage + (r & 1) * RSTRIDE;
        float* Pn = stage + ((r + 1) & 1) * RSTRIDE;
        if (r + 1 < R && tid < RSTRIDE / 4)
            cp16(Pn + tid * 4, g_blob + (size_t)(r + 1) * RSTRIDE + tid * 4);
        asm volatile("cp.async.commit_group;\n");

        const int tgt = ((const int*)P)[784 + wid];
        if (tgt >= 0) {
            const unsigned* s16 = (const unsigned*)P + wid * 16;
            const float*    ww  = P + 256 + wid * 32;
            const float     bt  = P[768 + wid];

            float a0 = 0.f, a1 = 0.f, a2 = 0.f, a3 = 0.f;
            #pragma unroll
            for (int q = 0; q < 8; q++) {
                unsigned u0 = s16[2 * q], u1 = s16[2 * q + 1];
                float4 w4 = *(const float4*)(ww + 4 * q);
                float v0 = stcol[u0 & 0xFFFFu];
                float v1 = stcol[u0 >> 16];
                float v2 = stcol[u1 & 0xFFFFu];
                float v3 = stcol[u1 >> 16];
                a0 = fmaf(v0, w4.x, a0);
                a1 = fmaf(v1, w4.y, a1);
                a2 = fmaf(v2, w4.z, a2);
                a3 = fmaf(v3, w4.w, a3);
            }
            float z = (a0 + a1) + (a2 + a3) + bt;
            float o = __fdividef(1.0f, 1.0f + __expf(-z));
            stcol[tgt] = o;
        }

        asm volatile("cp.async.wait_group 0;\n" ::: "memory");
        __syncthreads();
    }

    // ---- output: out[b][j] = st[768+j][col], 2 chunks of 32 outputs ----
    for (int ch = 0; ch < 2; ch++) {
        const int j0 = ch * 32;
        __syncthreads();
        #pragma unroll
        for (int i = 0; i < 2; i++) {
            int idx = tid + i * THREADS;
            int jj = idx >> 5, col = idx & 31;
            stage[col * 33 + jj] = st[(NUM_IN + NUM_HID + j0 + jj) * COLS + col];
        }
        __syncthreads();
        #pragma unroll
        for (int i = 0; i < 2; i++) {
            int idx = tid + i * THREADS;
            int row = idx >> 5, j = idx & 31;
            out[(size_t)(b0 + row) * NUM_OUT + j0 + j] = stage[row * 33 + j];
        }
    }
}

// ---------------------------------------------------------------------------
extern "C" void kernel_launch(void* const* d_in, const int* in_sizes, int n_in,
                              void* d_out, int out_size) {
    const float* x    = (const float*)d_in[0];
    const float* w    = (const float*)d_in[1];
    const float* bias = (const float*)d_in[2];
    const int*   src  = (const int*)d_in[3];
    float* out = (float*)d_out;
    (void)in_sizes; (void)n_in; (void)out_size;

    cudaFuncSetAttribute(neat_main_kernel,
                         cudaFuncAttributeMaxDynamicSharedMemorySize,
                         TOTAL_WORDS * 4);

    schedule_kernel<<<1, M_NODES>>>(src);
    blob_fill_kernel<<<RMAX, 256>>>(src, w, bias);
    neat_main_kernel<<<BATCH / COLS, THREADS, TOTAL_WORDS * 4>>>(x, out);
}

// round 6
// speedup vs baseline: 2.1025x; 2.1025x over previous
#include <cuda_runtime.h>
#include <cuda_fp16.h>
#include <cstdint>

#define BATCH   32768
#define NUM_IN  256
#define NUM_HID 512
#define NUM_OUT 64
#define M_NODES 576
#define N_NODES 832
#define KFAN    32
#define COLS    64             // batch columns per block (packed as 32 half2 words)
#define WPN     32             // u32 words per node row
#define THREADS 512            // 16 warps
#define SLOTS   16             // nodes per round (1 per warp)
#define RSTRIDE 800            // words/round: 256 src16 + 512 w + 16 bias + 16 tgt
#define RMAX    576
#define DUMMY   576            // dummy pred index, level pinned 0

// round-major param blob, per round r at r*RSTRIDE:
//   [0..256)    src16: two u16 (pred*32) word-offsets per u32
//   [256..768)  w
//   [768..784)  bias per slot
//   [784..800)  target word-offset (tgt_row*32) per slot, -1 = dummy
__device__ float g_blob[(size_t)RMAX * RSTRIDE];
__device__ int   g_sched[RMAX * SLOTS];
__device__ int   g_nrounds;

// ---------------------------------------------------------------------------
// Kernel A: ASAP levels via chunked Gauss-Seidel (preds in registers,
// fully unrolled scan), then counting-sort levels into rounds of <=16.
// ---------------------------------------------------------------------------
__global__ __launch_bounds__(M_NODES)
void schedule_kernel(const int* __restrict__ src) {
    __shared__ int lev[DUMMY + 32];       // lev[DUMMY..] pinned 0
    __shared__ int cnt[M_NODES + 1];
    __shared__ int rbase[M_NODES + 1];
    __shared__ int pos[M_NODES + 1];
    __shared__ int flag, lmax, R_sh;

    const int t = threadIdx.x;

    // preds in registers, padded with DUMMY
    int p[KFAN];
    #pragma unroll
    for (int k = 0; k < KFAN; k++) {
        int s = src[t * KFAN + k];
        p[k] = (s >= NUM_IN) ? (s - NUM_IN) : DUMMY;
    }
    lev[t] = 0;
    if (t < 32) lev[DUMMY + t] = 0;
    for (int i = t; i <= M_NODES; i += M_NODES) { cnt[i] = 0; pos[i] = 0; }
    if (t == 0) lmax = 0;
    __syncthreads();

    // 9 chunks of 64 consecutive nodes; preds are strictly lower-indexed
    for (int c = 0; c < M_NODES / 64; c++) {
        const bool mine = ((t >> 6) == c);
        while (true) {
            if (t == 0) flag = 0;
            __syncthreads();
            if (mine) {
                int m = 0;
                #pragma unroll
                for (int k = 0; k < KFAN; k++) {
                    int l = lev[p[k]];
                    m = (l > m) ? l : m;
                }
                if (m + 1 != lev[t]) { lev[t] = m + 1; flag = 1; }
            }
            __syncthreads();
            if (!flag) break;
        }
    }

    // histogram + max level
    atomicAdd(&cnt[lev[t]], 1);
    atomicMax(&lmax, lev[t]);
    __syncthreads();

    if (t == 0) {
        int r = 0;
        for (int L = 1; L <= lmax; L++) { rbase[L] = r; r += (cnt[L] + SLOTS - 1) >> 4; }
        R_sh = r;
        g_nrounds = r;
    }
    __syncthreads();

    for (int i = t; i < R_sh * SLOTS; i += M_NODES) g_sched[i] = -1;
    __syncthreads();

    {
        int L = lev[t];
        int q = atomicAdd(&pos[L], 1);
        g_sched[(rbase[L] + (q >> 4)) * SLOTS + (q & 15)] = t;
    }
}

// ---------------------------------------------------------------------------
// Kernel B: grid-parallel blob fill, one block per (used) round.
// ---------------------------------------------------------------------------
__global__ __launch_bounds__(256)
void blob_fill_kernel(const int* __restrict__ src,
                      const float* __restrict__ w,
                      const float* __restrict__ bias) {
    const int r = blockIdx.x;
    if (r >= g_nrounds) return;
    float* Pr = g_blob + (size_t)r * RSTRIDE;
    const int tid = threadIdx.x;

    {   // src16: premultiplied word offsets (pred * WPN)
        int slot = tid >> 4, j = tid & 15;
        int nd = g_sched[r * SLOTS + slot];
        unsigned v = 0;
        if (nd >= 0) {
            unsigned a = (unsigned)src[nd * KFAN + 2 * j] * WPN;
            unsigned b = (unsigned)src[nd * KFAN + 2 * j + 1] * WPN;
            v = (a & 0xFFFFu) | (b << 16);
        }
        ((unsigned*)Pr)[slot * 16 + j] = v;
    }
    #pragma unroll
    for (int u = 0; u < 2; u++) {
        int q = tid + u * 256;
        int slot = q >> 5, k = q & 31;
        int nd = g_sched[r * SLOTS + slot];
        Pr[256 + slot * 32 + k] = (nd >= 0) ? w[nd * KFAN + k] : 0.0f;
    }
    if (tid < SLOTS) {
        int nd = g_sched[r * SLOTS + tid];
        Pr[768 + tid] = (nd >= 0) ? bias[nd] : 0.0f;
        ((int*)Pr)[784 + tid] = (nd >= 0) ? (NUM_IN + nd) * WPN : -1;
    }
}

// ---------------------------------------------------------------------------
// Main kernel: 512 blocks x 512 threads, 2 blocks/SM. State = half2-packed:
// st[n][w] holds cols (2w, 2w+1) of node n. fp32 accumulation.
// ---------------------------------------------------------------------------
#define ST_WORDS    (N_NODES * WPN)                // 26624 u32
#define STAGE_WORDS 2112                           // 64x33 f32 staging >= 2*RSTRIDE
#define TOTAL_WORDS (ST_WORDS + STAGE_WORDS)       // 28736 -> 114944 B

extern __shared__ float smem_f[];

__device__ __forceinline__ void cp16(void* sdst, const void* gsrc) {
    uint32_t s = (uint32_t)__cvta_generic_to_shared(sdst);
    asm volatile("cp.async.cg.shared.global [%0], [%1], 16;\n" :: "r"(s), "l"(gsrc));
}

__global__ __launch_bounds__(THREADS, 2)
void neat_main_kernel(const float* __restrict__ x,
                      float* __restrict__ out) {
    uint32_t* st   = (uint32_t*)smem_f;            // [N_NODES][WPN] half2 words
    float*   stage = smem_f + ST_WORDS;            // staging / param double buffer

    const int tid  = threadIdx.x;
    const int wid  = tid >> 5;
    const int lane = tid & 31;
    const int b0   = blockIdx.x * COLS;
    const int R    = g_nrounds;

    // ---- input: x[b][n] f32 -> st[n] half2-packed; 8 chunks of 32 inputs ----
    for (int ch = 0; ch < 8; ch++) {
        const int nc0 = ch * 32;
        __syncthreads();
        #pragma unroll
        for (int i = 0; i < 4; i++) {
            int idx = tid + i * THREADS;           // 2048 = 64 rows x 32 cols
            int row = idx >> 5, c = idx & 31;
            stage[row * 33 + c] = x[(size_t)(b0 + row) * NUM_IN + nc0 + c];
        }
        __syncthreads();
        #pragma unroll
        for (int i = 0; i < 2; i++) {
            int idx = tid + i * THREADS;           // 1024 = 32 nodes x 32 words
            int n = idx >> 5, wc = idx & 31;
            float lo = stage[(2 * wc) * 33 + n];
            float hi = stage[(2 * wc + 1) * 33 + n];
            __half2 h = __floats2half2_rn(lo, hi);
            st[(nc0 + n) * WPN + wc] = *(uint32_t*)&h;
        }
    }
    __syncthreads();

    // ---- prefetch round 0 params ----
    if (tid < RSTRIDE / 4) cp16(stage + tid * 4, g_blob + tid * 4);
    asm volatile("cp.async.commit_group;\n");
    asm volatile("cp.async.wait_group 0;\n" ::: "memory");
    __syncthreads();

    uint32_t* stc = st + lane;                     // lane owns cols (2*lane, 2*lane+1)

    // ---- main rounds: warp wid evaluates slot wid over 64 columns ----
    for (int r = 0; r < R; r++) {
        float* P  = stage + (r & 1) * RSTRIDE;
        float* Pn = stage + ((r + 1) & 1) * RSTRIDE;
        if (r + 1 < R && tid < RSTRIDE / 4)
            cp16(Pn + tid * 4, g_blob + (size_t)(r + 1) * RSTRIDE + tid * 4);
        asm volatile("cp.async.commit_group;\n");

        const int tgt = ((const int*)P)[784 + wid];
        if (tgt >= 0) {
            const uint4* s4 = (const uint4*)((const unsigned*)P + wid * 16);
            uint4 sa = s4[0], sb = s4[1], sc = s4[2], sd = s4[3];
            const float* ww = P + 256 + wid * 32;
            const float  bt = P[768 + wid];

            float ax = 0.f, ay = 0.f, bx = 0.f, by = 0.f;
            float cx = 0.f, cy = 0.f, dx = 0.f, dy = 0.f;
            unsigned su[16] = {sa.x, sa.y, sa.z, sa.w, sb.x, sb.y, sb.z, sb.w,
                               sc.x, sc.y, sc.z, sc.w, sd.x, sd.y, sd.z, sd.w};
            #pragma unroll
            for (int q = 0; q < 8; q++) {
                unsigned u0 = su[2 * q], u1 = su[2 * q + 1];
                float4 w4 = *(const float4*)(ww + 4 * q);
                uint32_t p0 = stc[u0 & 0xFFFFu];
                uint32_t p1 = stc[u0 >> 16];
                uint32_t p2 = stc[u1 & 0xFFFFu];
                uint32_t p3 = stc[u1 >> 16];
                float2 v0 = __half22float2(*(__half2*)&p0);
                float2 v1 = __half22float2(*(__half2*)&p1);
                float2 v2 = __half22float2(*(__half2*)&p2);
                float2 v3 = __half22float2(*(__half2*)&p3);
                ax = fmaf(v0.x, w4.x, ax);  ay = fmaf(v0.y, w4.x, ay);
                bx = fmaf(v1.x, w4.y, bx);  by = fmaf(v1.y, w4.y, by);
                cx = fmaf(v2.x, w4.z, cx);  cy = fmaf(v2.y, w4.z, cy);
                dx = fmaf(v3.x, w4.w, dx);  dy = fmaf(v3.y, w4.w, dy);
            }
            float z0 = (ax + bx) + (cx + dx) + bt;
            float z1 = (ay + by) + (cy + dy) + bt;
            float o0 = __fdividef(1.0f, 1.0f + __expf(-z0));
            float o1 = __fdividef(1.0f, 1.0f + __expf(-z1));
            __half2 h = __floats2half2_rn(o0, o1);
            stc[tgt] = *(uint32_t*)&h;
        }

        asm volatile("cp.async.wait_group 0;\n" ::: "memory");
        __syncthreads();
    }

    // ---- output: out[b][j] f32; 2 chunks of 32 output nodes ----
    for (int ch = 0; ch < 2; ch++) {
        const int j0 = ch * 32;
        __syncthreads();
        #pragma unroll
        for (int i = 0; i < 2; i++) {
            int idx = tid + i * THREADS;           // 1024 = 32 j x 32 words
            int j = idx >> 5, wc = idx & 31;
            uint32_t u = st[(NUM_IN + NUM_HID + j0 + j) * WPN + wc];
            float2 v = __half22float2(*(__half2*)&u);
            stage[(2 * wc) * 33 + j]     = v.x;
            stage[(2 * wc + 1) * 33 + j] = v.y;
        }
        __syncthreads();
        #pragma unroll
        for (int i = 0; i < 4; i++) {
            int idx = tid + i * THREADS;           // 2048 = 64 rows x 32 j
            int row = idx >> 5, j = idx & 31;
            out[(size_t)(b0 + row) * NUM_OUT + j0 + j] = stage[row * 33 + j];
        }
    }
}

// ---------------------------------------------------------------------------
extern "C" void kernel_launch(void* const* d_in, const int* in_sizes, int n_in,
                              void* d_out, int out_size) {
    const float* x    = (const float*)d_in[0];
    const float* w    = (const float*)d_in[1];
    const float* bias = (const float*)d_in[2];
    const int*   src  = (const int*)d_in[3];
    float* out = (float*)d_out;
    (void)in_sizes; (void)n_in; (void)out_size;

    cudaFuncSetAttribute(neat_main_kernel,
                         cudaFuncAttributeMaxDynamicSharedMemorySize,
                         TOTAL_WORDS * 4);

    schedule_kernel<<<1, M_NODES>>>(src);
    blob_fill_kernel<<<RMAX, 256>>>(src, w, bias);
    neat_main_kernel<<<BATCH / COLS, THREADS, TOTAL_WORDS * 4>>>(x, out);
}